// round 7
// baseline (speedup 1.0000x reference)
#include <cuda_runtime.h>
#include <cuda_bf16.h>
#include <cstdint>

// OHEM smooth-L1 loss. y_pred,y_true: [64, 262144] fp32 -> scalar fp32.
//  pass_a: sweep; stage "interesting" (p,t) pairs (pos OR |p|>=1.5625) in private
//          smem slots; phase 2 -> pos stats + counts-only 2048-bin hist (global
//          RED) + big-neg a-sum; per-warp shuffle reduce + direct atomics.
//  pass_e: 1 block/row (1024 thr): top-k threshold from L2-hot hist, neg sum via
//          linear reconstruction (sum_sel = suma - unsel - k/2); rare exact
//          fallback; global ticket -> final scalar. Self-cleans scratch for the
//          next graph replay (no memset launch).

static constexpr int B = 64;
static constexpr int N = 256 * 256 * 4;        // 262144
static constexpr int NBINS = 2048;
static constexpr unsigned CUT_BITS = 0x3FC80000u;   // 1.5625f
static constexpr float   CUTF = 1.5625f;

static constexpr int TPB = 256;
static constexpr int VEC = 4;
static constexpr int ITERS = 4;
static constexpr int EPB = TPB * VEC * ITERS;   // 4096
static constexpr int BPR = N / EPB;             // 64

static constexpr int TPE = 1024;                // pass_e block size

struct Scratch {
    unsigned hist[B][NBINS];
    unsigned pos_cnt[B];
    unsigned big_cnt[B];
    double   pos_sum[B];
    double   big_suma[B];
    double   ns, nc;
    unsigned ticket2;
};
__device__ Scratch g_z;        // zero at load; kernels restore zeros themselves

// valid in thread 0; internally barriered; all threads must call
__device__ double block_reduce_double(double v) {
    __shared__ double sh[32];
    int lane = threadIdx.x & 31, w = threadIdx.x >> 5;
    #pragma unroll
    for (int o = 16; o; o >>= 1) v += __shfl_down_sync(0xffffffffu, v, o);
    __syncthreads();
    if (lane == 0) sh[w] = v;
    __syncthreads();
    double r = 0.0;
    if (w == 0) {
        int nw = (blockDim.x + 31) >> 5;
        r = (lane < nw) ? sh[lane] : 0.0;
        #pragma unroll
        for (int o = 16; o; o >>= 1) r += __shfl_down_sync(0xffffffffu, r, o);
    }
    __syncthreads();
    return r;
}

__device__ __forceinline__ float fsl1(float a) {
    float u = fminf(a, 1.0f);
    return fmaf(u, fmaf(0.5f, u, -1.0f), a);   // exact smooth_l1, branch-free
}
__device__ __forceinline__ float bin_center(int b) {
    return __uint_as_float(CUT_BITS + ((unsigned)b << 13) + (1u << 12));
}

// warp-0 suffix select: find b*, c = count(bins > b*), c < keff <= c + h[b*]
__device__ void warp_select(const unsigned* h, int nbins, unsigned keff,
                            int* out_b, unsigned* out_c) {
    const int lane = threadIdx.x;              // caller guards tid < 32
    const int chunk = nbins >> 5;
    unsigned cs = 0;
    for (int j = 0; j < chunk; j++) cs += h[lane * chunk + j];
    unsigned v = cs;
    #pragma unroll
    for (int off = 1; off < 32; off <<= 1) {
        unsigned g = __shfl_down_sync(0xffffffffu, v, off);
        if (lane + off < 32) v += g;
    }
    unsigned vnext = __shfl_down_sync(0xffffffffu, v, 1);
    if (lane == 31) vnext = 0u;
    bool hit = (v >= keff) && (vnext < keff);
    unsigned hb = __ballot_sync(0xffffffffu, hit);
    int c = __ffs(hb) - 1;
    unsigned S = __shfl_sync(0xffffffffu, vnext, c);
    for (int g = (chunk >> 5) - 1; g >= 0; g--) {
        unsigned hv = h[c * chunk + g * 32 + lane];
        unsigned w = hv;
        #pragma unroll
        for (int off = 1; off < 32; off <<= 1) {
            unsigned gg = __shfl_down_sync(0xffffffffu, w, off);
            if (lane + off < 32) w += gg;
        }
        unsigned wnext = __shfl_down_sync(0xffffffffu, w, 1);
        if (lane == 31) wnext = 0u;
        unsigned tot = __shfl_sync(0xffffffffu, w, 0);
        bool hit2 = (S + w >= keff) && (S + wnext < keff);
        unsigned hb2 = __ballot_sync(0xffffffffu, hit2);
        if (hb2) {
            int l = __ffs(hb2) - 1;
            unsigned wl = __shfl_sync(0xffffffffu, w, l);
            unsigned hl = __shfl_sync(0xffffffffu, hv, l);
            if (lane == 0) { *out_b = c * chunk + g * 32 + l; *out_c = S + wl - hl; }
            return;
        }
        S += tot;
    }
}

// ---------------- Pass A: data sweep -----------------------------------------
__global__ void __launch_bounds__(TPB) pass_a(const float* __restrict__ yp,
                                              const float* __restrict__ yt) {
    __shared__ float2 sbuf[TPB][17];            // 16 slots + pad; 34.8 KB
    const int r = blockIdx.y;
    const int tid = threadIdx.x;
    const unsigned lane = tid & 31u;
    const size_t base = (size_t)r * N + (size_t)blockIdx.x * EPB;
    int cnt = 0;

    // phase 1: filter + stage (1 FFMA + 1 FSETP + predicated STS.64 per elem)
    #pragma unroll
    for (int it = 0; it < ITERS; it++) {
        size_t idx = base + (size_t)it * (TPB * VEC) + (size_t)tid * VEC;
        float4 p = *reinterpret_cast<const float4*>(yp + idx);
        float4 t = *reinterpret_cast<const float4*>(yt + idx);
        float pv[4] = {p.x, p.y, p.z, p.w};
        float tv[4] = {t.x, t.y, t.z, t.w};
        #pragma unroll
        for (int j = 0; j < 4; j++) {
            // t!=0 -> w huge; t==0 -> w=|p|.  interesting <=> w >= CUTF
            float w = fmaf(fabsf(tv[j]), 1e38f, fabsf(pv[j]));
            if (w >= CUTF) { sbuf[tid][cnt] = make_float2(pv[j], tv[j]); cnt++; }
        }
    }

    // phase 2: process staged entries (private slots; no sync needed)
    float psum = 0.f, bsum = 0.f; int pc = 0, bc = 0;
    for (int c = 0; c < cnt; c++) {
        float2 e = sbuf[tid][c];
        if (e.y != 0.f) {                        // positive
            psum += fsl1(fabsf(e.x - e.y));
            pc++;
        } else {                                 // big negative (|p| >= 1.5625)
            float a = fabsf(e.x);
            unsigned bin = (__float_as_uint(a) - CUT_BITS) >> 13;
            bin = min(bin, (unsigned)(NBINS - 1));
            atomicAdd(&g_z.hist[r][bin], 1u);    // fire-and-forget RED
            bsum += a; bc++;
        }
    }

    // per-warp shuffle reduction + direct global atomics (no barriers, no fence)
    #pragma unroll
    for (int o = 16; o; o >>= 1) {
        psum += __shfl_down_sync(0xffffffffu, psum, o);
        bsum += __shfl_down_sync(0xffffffffu, bsum, o);
        pc   += __shfl_down_sync(0xffffffffu, pc, o);
        bc   += __shfl_down_sync(0xffffffffu, bc, o);
    }
    if (lane == 0) {
        if (pc) { atomicAdd(&g_z.pos_sum[r], (double)psum); atomicAdd(&g_z.pos_cnt[r], (unsigned)pc); }
        if (bc) { atomicAdd(&g_z.big_suma[r], (double)bsum); atomicAdd(&g_z.big_cnt[r], (unsigned)bc); }
    }
}

// ---------------- Pass E: row finish + final scalar + self-clean -------------
__global__ void __launch_bounds__(TPE) pass_e(const float* __restrict__ yp,
                                              const float* __restrict__ yt,
                                              float* __restrict__ out) {
    const int r = blockIdx.x, tid = threadIdx.x;
    __shared__ unsigned s_h[NBINS];
    __shared__ float    s_f[NBINS];
    __shared__ int s_b; __shared__ unsigned s_c;
    __shared__ int s_fin2;

    // snapshot hist to smem, then zero the global copy for the next replay
    for (int i = tid; i < NBINS; i += TPE) {
        s_h[i] = g_z.hist[r][i];
        g_z.hist[r][i] = 0u;
    }
    __syncthreads();

    const unsigned pcr = g_z.pos_cnt[r];
    const unsigned bcr = g_z.big_cnt[r];
    const double   bsa = g_z.big_suma[r];
    if (tid == 0) { g_z.big_cnt[r] = 0u; g_z.big_suma[r] = 0.0; }
    unsigned k = 2u * pcr; if (k > (unsigned)(N - 1)) k = (unsigned)(N - 1);
    const unsigned keff = (k < bcr) ? k : bcr;

    double negr = 0.0;                          // meaningful in tid 0
    if (keff > 0) {
        if (tid < 32) warp_select(s_h, NBINS, keff, &s_b, &s_c);
        __syncthreads();
        const int b1 = s_b; const unsigned cab = s_c;
        double unsel = 0.0;                     // a-sum over unselected bigs
        for (int b = tid; b < b1; b += TPE)
            unsel += (double)s_h[b] * (double)bin_center(b);
        unsel = block_reduce_double(unsel);
        if (tid == 0) {
            unsigned part_unsel = s_h[b1] - (keff - cab);
            unsel += (double)part_unsel * (double)bin_center(b1);
            negr = bsa - unsel - 0.5 * (double)keff;
        }
    }

    // rare fallback: k exceeds big count -> top (k-bc) among below-cut negs
    if (bcr < k) {
        __syncthreads();
        for (int i = tid; i < NBINS; i += TPE) { s_h[i] = 0u; s_f[i] = 0.f; }
        __syncthreads();
        const size_t rb = (size_t)r * N;
        for (int i = tid; i < N; i += TPE) {
            float p = yp[rb + i], t = yt[rb + i];
            if (t == 0.f) {
                float a = fabsf(p);
                if (a < CUTF) {
                    unsigned bin = __float_as_uint(a) >> 19;
                    bin = min(bin, (unsigned)(NBINS - 1));
                    atomicAdd(&s_h[bin], 1u);
                    atomicAdd(&s_f[bin], fsl1(a));
                }
            }
        }
        __syncthreads();
        double dt = 0.0;
        for (int i = tid; i < NBINS; i += TPE) dt += (double)s_h[i];
        dt = block_reduce_double(dt);
        if (tid == 0) s_c = (unsigned)(dt + 0.5);
        __syncthreads();
        unsigned tot = s_c;
        __syncthreads();
        unsigned kc = k - bcr; if (kc > tot) kc = tot;
        if (kc > 0) {
            if (tid < 32) warp_select(s_h, NBINS, kc, &s_b, &s_c);
            __syncthreads();
            const int b1 = s_b; const unsigned cab = s_c;
            double ext = 0.0;
            for (int b = b1 + 1 + tid; b < NBINS; b += TPE) ext += (double)s_f[b];
            ext = block_reduce_double(ext);
            if (tid == 0) {
                unsigned part = kc - cab;
                if (s_h[b1]) ext += (double)part * ((double)s_f[b1] / (double)s_h[b1]);
                negr += ext;
            }
        }
    }

    if (tid == 0) {
        atomicAdd(&g_z.ns, negr);
        atomicAdd(&g_z.nc, (double)k);
        __threadfence();
        s_fin2 = (atomicAdd(&g_z.ticket2, 1u) == (unsigned)(B - 1)) ? 1 : 0;
    }
    __syncthreads();
    if (!s_fin2) return;

    // ---- final scalar (one block total) + clean remaining scratch ----
    __threadfence();
    double ps  = (tid < B) ? g_z.pos_sum[tid] : 0.0;
    double pcs = (tid < B) ? (double)g_z.pos_cnt[tid] : 0.0;
    ps = block_reduce_double(ps);
    pcs = block_reduce_double(pcs);
    if (tid == 0) {
        double NS = g_z.ns, NC = g_z.nc;
        double pos_loss = (pcs > 0.0) ? ps / pcs : 0.0;
        double neg_loss = (NC > 0.0) ? NS / NC : 0.0;
        out[0] = (float)(2.0 * pos_loss + neg_loss);
        g_z.ns = 0.0; g_z.nc = 0.0; g_z.ticket2 = 0u;
    }
    if (tid < B) { g_z.pos_sum[tid] = 0.0; g_z.pos_cnt[tid] = 0u; }
}

// ---------------- launch ------------------------------------------------------
extern "C" void kernel_launch(void* const* d_in, const int* in_sizes, int n_in,
                              void* d_out, int out_size) {
    const float* yp = (const float*)d_in[0];
    const float* yt = (const float*)d_in[1];
    float* out = (float*)d_out;

    pass_a<<<dim3(BPR, B), TPB>>>(yp, yt);
    pass_e<<<B, TPE>>>(yp, yt, out);
}

// round 8
// speedup vs baseline: 6.2481x; 6.2481x over previous
#include <cuda_runtime.h>
#include <cuda_bf16.h>
#include <cstdint>

// OHEM smooth-L1 loss. y_pred,y_true: [64, 262144] fp32 -> scalar fp32.
//  memset : zero scratch (513 KB).
//  pass_a : sweep; stage "interesting" (p,t) pairs (pos OR |p|>=1.5625) in
//           private smem slots; phase 2 -> pos stats + counts-only 2048-bin
//           hist (global RED) + big-neg a-sum. Warp shuffle reduce + smem
//           combine -> 4 atomics/block (1 barrier total).
//  pass_e : 4 blocks x 1024 thr, 16 rows/block, one WARP per row: top-k
//           threshold select + neg-sum linear reconstruction entirely
//           warp-local over 128KB smem-resident histograms. Rare exact
//           fallback per flagged row. 4-block ticket -> final scalar.

static constexpr int B = 64;
static constexpr int N = 256 * 256 * 4;        // 262144
static constexpr int NBINS = 2048;
static constexpr unsigned CUT_BITS = 0x3FC80000u;   // 1.5625f
static constexpr float   CUTF = 1.5625f;

static constexpr int TPB = 256;
static constexpr int VEC = 4;
static constexpr int ITERS = 4;
static constexpr int EPB = TPB * VEC * ITERS;   // 4096
static constexpr int BPR = N / EPB;             // 64

static constexpr int RPB_E = 16;                // rows per pass_e block
static constexpr int GRID_E = B / RPB_E;        // 4
static constexpr int TPE = 1024;

struct Zeroed {
    unsigned hist[B][NBINS];
    unsigned pos_cnt[B];
    unsigned big_cnt[B];
    double   pos_sum[B];
    double   big_suma[B];
    double   ns, nc;
    unsigned ticket;
};
__device__ Zeroed g_z;         // ~513 KB memset per launch

__device__ __forceinline__ float fsl1(float a) {
    float u = fminf(a, 1.0f);
    return fmaf(u, fmaf(0.5f, u, -1.0f), a);   // exact smooth_l1, branch-free
}
__device__ __forceinline__ float bin_center(int b) {
    return __uint_as_float(CUT_BITS + ((unsigned)b << 13) + (1u << 12));
}

// valid in thread 0; internally barriered; all threads must call
__device__ double block_reduce_double(double v) {
    __shared__ double sh[32];
    int lane = threadIdx.x & 31, w = threadIdx.x >> 5;
    #pragma unroll
    for (int o = 16; o; o >>= 1) v += __shfl_down_sync(0xffffffffu, v, o);
    __syncthreads();
    if (lane == 0) sh[w] = v;
    __syncthreads();
    double r = 0.0;
    if (w == 0) {
        int nw = (blockDim.x + 31) >> 5;
        r = (lane < nw) ? sh[lane] : 0.0;
        #pragma unroll
        for (int o = 16; o; o >>= 1) r += __shfl_down_sync(0xffffffffu, r, o);
    }
    __syncthreads();
    return r;
}

// Warp-local suffix select over nbins=2048 hist. ALL 32 lanes of the calling
// warp must be active; returns b*, c = count(bins > b*), c < keff <= c + h[b*]
// in every lane.
__device__ void warp_select2(const unsigned* h, unsigned keff,
                             int& ob, unsigned& oc) {
    const int lane = threadIdx.x & 31;
    const int chunk = NBINS >> 5;              // 64
    unsigned cs = 0;
    #pragma unroll 8
    for (int j = 0; j < chunk; j++) cs += h[lane * chunk + j];
    unsigned v = cs;
    #pragma unroll
    for (int off = 1; off < 32; off <<= 1) {
        unsigned g = __shfl_down_sync(0xffffffffu, v, off);
        if (lane + off < 32) v += g;
    }
    unsigned vnext = __shfl_down_sync(0xffffffffu, v, 1);
    if (lane == 31) vnext = 0u;
    bool hit = (v >= keff) && (vnext < keff);
    unsigned hb = __ballot_sync(0xffffffffu, hit);
    int c = __ffs(hb) - 1;
    unsigned S = __shfl_sync(0xffffffffu, vnext, c);
    ob = 0; oc = 0;
    #pragma unroll
    for (int g = (chunk >> 5) - 1; g >= 0; g--) {
        unsigned hv = h[c * chunk + g * 32 + lane];
        unsigned w = hv;
        #pragma unroll
        for (int off = 1; off < 32; off <<= 1) {
            unsigned gg = __shfl_down_sync(0xffffffffu, w, off);
            if (lane + off < 32) w += gg;
        }
        unsigned wnext = __shfl_down_sync(0xffffffffu, w, 1);
        if (lane == 31) wnext = 0u;
        unsigned tot = __shfl_sync(0xffffffffu, w, 0);
        bool hit2 = (S + w >= keff) && (S + wnext < keff);
        unsigned hb2 = __ballot_sync(0xffffffffu, hit2);
        if (hb2) {
            int l = __ffs(hb2) - 1;
            unsigned wl = __shfl_sync(0xffffffffu, w, l);
            unsigned hl = __shfl_sync(0xffffffffu, hv, l);
            ob = c * chunk + g * 32 + l;
            oc = S + wl - hl;
            return;
        }
        S += tot;
    }
}

// ---------------- Pass A: data sweep -----------------------------------------
__global__ void __launch_bounds__(TPB) pass_a(const float* __restrict__ yp,
                                              const float* __restrict__ yt) {
    __shared__ float2 sbuf[TPB][17];            // 16 slots + pad; 34.8 KB
    __shared__ float rs_ps[8], rs_bs[8];
    __shared__ int   rs_pc[8], rs_bc[8];
    const int r = blockIdx.y;
    const int tid = threadIdx.x;
    const unsigned lane = tid & 31u;
    const int w = tid >> 5;
    const size_t base = (size_t)r * N + (size_t)blockIdx.x * EPB;
    int cnt = 0;

    // phase 1: filter + stage (1 FFMA + 1 FSETP + predicated STS.64 per elem)
    #pragma unroll
    for (int it = 0; it < ITERS; it++) {
        size_t idx = base + (size_t)it * (TPB * VEC) + (size_t)tid * VEC;
        float4 p = *reinterpret_cast<const float4*>(yp + idx);
        float4 t = *reinterpret_cast<const float4*>(yt + idx);
        float pv[4] = {p.x, p.y, p.z, p.w};
        float tv[4] = {t.x, t.y, t.z, t.w};
        #pragma unroll
        for (int j = 0; j < 4; j++) {
            // t!=0 -> w huge; t==0 -> w=|p|.  interesting <=> w >= CUTF
            float wv = fmaf(fabsf(tv[j]), 1e38f, fabsf(pv[j]));
            if (wv >= CUTF) { sbuf[tid][cnt] = make_float2(pv[j], tv[j]); cnt++; }
        }
    }

    // phase 2: process staged entries (private slots; no sync needed)
    float psum = 0.f, bsum = 0.f; int pc = 0, bc = 0;
    for (int c = 0; c < cnt; c++) {
        float2 e = sbuf[tid][c];
        if (e.y != 0.f) {                        // positive
            psum += fsl1(fabsf(e.x - e.y));
            pc++;
        } else {                                 // big negative (|p| >= 1.5625)
            float a = fabsf(e.x);
            unsigned bin = (__float_as_uint(a) - CUT_BITS) >> 13;
            bin = min(bin, (unsigned)(NBINS - 1));
            atomicAdd(&g_z.hist[r][bin], 1u);    // fire-and-forget RED
            bsum += a; bc++;
        }
    }

    // per-warp shuffle reduce -> smem -> thread 0 -> 4 atomics (1 barrier)
    #pragma unroll
    for (int o = 16; o; o >>= 1) {
        psum += __shfl_down_sync(0xffffffffu, psum, o);
        bsum += __shfl_down_sync(0xffffffffu, bsum, o);
        pc   += __shfl_down_sync(0xffffffffu, pc, o);
        bc   += __shfl_down_sync(0xffffffffu, bc, o);
    }
    if (lane == 0) { rs_ps[w] = psum; rs_bs[w] = bsum; rs_pc[w] = pc; rs_bc[w] = bc; }
    __syncthreads();
    if (tid == 0) {
        double PS = 0.0, BS = 0.0; int PC = 0, BC = 0;
        #pragma unroll
        for (int i = 0; i < 8; i++) {
            PS += (double)rs_ps[i]; BS += (double)rs_bs[i];
            PC += rs_pc[i]; BC += rs_bc[i];
        }
        if (PC) { atomicAdd(&g_z.pos_sum[r], PS); atomicAdd(&g_z.pos_cnt[r], (unsigned)PC); }
        if (BC) { atomicAdd(&g_z.big_suma[r], BS); atomicAdd(&g_z.big_cnt[r], (unsigned)BC); }
    }
}

// ---------------- Pass E: 4 blocks, one warp per row -------------------------
extern __shared__ unsigned dyn_s[];             // RPB_E * NBINS u32 = 128 KB

__global__ void __launch_bounds__(TPE) pass_e(const float* __restrict__ yp,
                                              const float* __restrict__ yt,
                                              float* __restrict__ out) {
    const int tid = threadIdx.x;
    const int row0 = blockIdx.x * RPB_E;
    unsigned (*s_h)[NBINS] = reinterpret_cast<unsigned(*)[NBINS]>(dyn_s);
    __shared__ double s_negr[RPB_E];
    __shared__ double s_kd[RPB_E];
    __shared__ int    s_fb[RPB_E];
    __shared__ int s_b; __shared__ unsigned s_c;
    __shared__ int s_last;

    // cooperative load of 16 row histograms (128 KB) via uint4
    {
        const uint4* src = reinterpret_cast<const uint4*>(&g_z.hist[row0][0]);
        uint4* dst = reinterpret_cast<uint4*>(dyn_s);
        #pragma unroll
        for (int i = 0; i < RPB_E * NBINS / 4 / TPE; i++)
            dst[i * TPE + tid] = src[i * TPE + tid];
    }
    __syncthreads();

    const int w = tid >> 5, lane = tid & 31;
    if (w < RPB_E) {
        const int r = row0 + w;
        const unsigned pcr = g_z.pos_cnt[r];
        const unsigned bcr = g_z.big_cnt[r];
        const double   bsa = g_z.big_suma[r];
        unsigned k = 2u * pcr; if (k > (unsigned)(N - 1)) k = (unsigned)(N - 1);
        const unsigned keff = (k < bcr) ? k : bcr;
        double negr = 0.0;
        if (keff > 0) {
            int b1; unsigned cab;
            warp_select2(s_h[w], keff, b1, cab);
            double acc = 0.0;                   // a-sum over unselected bigs
            for (int b = lane; b < b1; b += 32)
                acc += (double)s_h[w][b] * (double)bin_center(b);
            #pragma unroll
            for (int o = 16; o; o >>= 1) acc += __shfl_down_sync(0xffffffffu, acc, o);
            if (lane == 0) {
                unsigned part_unsel = s_h[w][b1] - (keff - cab);
                acc += (double)part_unsel * (double)bin_center(b1);
                negr = bsa - acc - 0.5 * (double)keff;
            }
        }
        if (lane == 0) { s_negr[w] = negr; s_kd[w] = (double)k; s_fb[w] = (bcr < k); }
    }
    __syncthreads();

    // rare fallback: whole block per flagged row (top k-bc among below-cut negs)
    for (int w2 = 0; w2 < RPB_E; w2++) {
        if (!s_fb[w2]) continue;
        const int r = row0 + w2;
        unsigned* f_h = s_h[0];
        float*    f_f = reinterpret_cast<float*>(s_h[1]);
        for (int i = tid; i < NBINS; i += TPE) { f_h[i] = 0u; f_f[i] = 0.f; }
        __syncthreads();
        const size_t rb = (size_t)r * N;
        for (int i = tid; i < N; i += TPE) {
            float p = yp[rb + i], t = yt[rb + i];
            if (t == 0.f) {
                float a = fabsf(p);
                if (a < CUTF) {
                    unsigned bin = __float_as_uint(a) >> 19;
                    bin = min(bin, (unsigned)(NBINS - 1));
                    atomicAdd(&f_h[bin], 1u);
                    atomicAdd(&f_f[bin], fsl1(a));
                }
            }
        }
        __syncthreads();
        double dt = 0.0;
        for (int i = tid; i < NBINS; i += TPE) dt += (double)f_h[i];
        dt = block_reduce_double(dt);
        if (tid == 0) s_c = (unsigned)(dt + 0.5);
        __syncthreads();
        unsigned tot = s_c;
        unsigned k2 = (unsigned)(s_kd[w2] + 0.5);
        unsigned bcr = g_z.big_cnt[r];
        unsigned kc = k2 - bcr; if (kc > tot) kc = tot;
        __syncthreads();
        if (kc > 0) {
            if (tid < 32) {
                int b1; unsigned cab;
                warp_select2(f_h, kc, b1, cab);
                if (lane == 0) { s_b = b1; s_c = cab; }
            }
            __syncthreads();
            const int b1 = s_b; const unsigned cab = s_c;
            double ext = 0.0;
            for (int b = b1 + 1 + tid; b < NBINS; b += TPE) ext += (double)f_f[b];
            ext = block_reduce_double(ext);
            if (tid == 0) {
                unsigned part = kc - cab;
                if (f_h[b1]) ext += (double)part * ((double)f_f[b1] / (double)f_h[b1]);
                s_negr[w2] += ext;
            }
            __syncthreads();
        }
    }

    if (tid < RPB_E) {
        atomicAdd(&g_z.ns, s_negr[tid]);
        atomicAdd(&g_z.nc, s_kd[tid]);
    }
    __threadfence();
    __syncthreads();
    if (tid == 0)
        s_last = (atomicAdd(&g_z.ticket, 1u) == (unsigned)(GRID_E - 1)) ? 1 : 0;
    __syncthreads();
    if (!s_last) return;

    // ---- final scalar (one block total) ----
    __threadfence();
    double ps  = (tid < B) ? g_z.pos_sum[tid] : 0.0;
    double pcs = (tid < B) ? (double)g_z.pos_cnt[tid] : 0.0;
    ps = block_reduce_double(ps);
    pcs = block_reduce_double(pcs);
    if (tid == 0) {
        double NS = g_z.ns, NC = g_z.nc;
        double pos_loss = (pcs > 0.0) ? ps / pcs : 0.0;
        double neg_loss = (NC > 0.0) ? NS / NC : 0.0;
        out[0] = (float)(2.0 * pos_loss + neg_loss);
    }
}

// ---------------- launch ------------------------------------------------------
extern "C" void kernel_launch(void* const* d_in, const int* in_sizes, int n_in,
                              void* d_out, int out_size) {
    const float* yp = (const float*)d_in[0];
    const float* yt = (const float*)d_in[1];
    float* out = (float*)d_out;

    static bool attr_set = false;
    if (!attr_set) {
        cudaFuncSetAttribute(pass_e, cudaFuncAttributeMaxDynamicSharedMemorySize,
                             RPB_E * NBINS * (int)sizeof(unsigned));
        attr_set = true;
    }

    void* zp = nullptr;
    cudaGetSymbolAddress(&zp, g_z);
    cudaMemsetAsync(zp, 0, sizeof(Zeroed));

    pass_a<<<dim3(BPR, B), TPB>>>(yp, yt);
    pass_e<<<GRID_E, TPE, RPB_E * NBINS * sizeof(unsigned)>>>(yp, yt, out);
}